// round 15
// baseline (speedup 1.0000x reference)
#include <cuda_runtime.h>
#include <cuda_fp16.h>
#include <cstdint>
#include <stdint.h>
#include <math.h>

#define N_NODES 8192
#define K_NB    32
#define D_DIM   128
#define H_DIM   256
#define NGROUPS 2048     // 4 nodes per group -> M = 128 rows
#define MAXG    14
#define THREADS 512

typedef unsigned int       u32;
typedef unsigned long long u64;

__device__ float g_P[N_NODES * H_DIM];   // x @ W1[:128] + b1
__device__ float g_Q[N_NODES * H_DIM];   // x @ W1[128:]
// W2^T fp16 swizzled smem image: row n (512B = 256 k), 128KB
__device__ __align__(16) unsigned char g_W2h[131072];

// ---------------- helpers ----------------
__device__ __forceinline__ u32 smem_u32(const void* p) {
    return (u32)__cvta_generic_to_shared(p);
}
__device__ __forceinline__ void cp_async16(u32 saddr, const void* gaddr) {
    asm volatile("cp.async.cg.shared.global [%0], [%1], 16;" :: "r"(saddr), "l"(gaddr));
}
__device__ __forceinline__ void cp_commit() { asm volatile("cp.async.commit_group;"); }
__device__ __forceinline__ void cp_wait0() {
    asm volatile("cp.async.wait_group 0;" ::: "memory");
}
__device__ __forceinline__ void ldsm4(u32* r, u32 addr) {
    asm volatile("ldmatrix.sync.aligned.m8n8.x4.shared.b16 {%0,%1,%2,%3}, [%4];"
                 : "=r"(r[0]), "=r"(r[1]), "=r"(r[2]), "=r"(r[3]) : "r"(addr));
}
__device__ __forceinline__ void mma_f16(float* c, const u32* a, const u32* b) {
    asm volatile(
        "mma.sync.aligned.m16n8k16.row.col.f32.f16.f16.f32 "
        "{%0,%1,%2,%3}, {%4,%5,%6,%7}, {%8,%9}, {%0,%1,%2,%3};"
        : "+f"(c[0]), "+f"(c[1]), "+f"(c[2]), "+f"(c[3])
        : "r"(a[0]), "r"(a[1]), "r"(a[2]), "r"(a[3]), "r"(b[0]), "r"(b[1]));
}

// build 64 k-values (fp16) for one h1 row slice; Q loaded here (LDG)
__device__ __forceinline__ void build_slice(
    const float* Qn, const float* Pn, int ks, int row,
    unsigned char* h1_p)
{
    const float4* qp = (const float4*)(Qn + ks);
    const float4* pp = (const float4*)(Pn + ks);
    float4 qv[16];
    #pragma unroll
    for (int i = 0; i < 16; i++) qv[i] = qp[i];
    const u32 swz = (u32)((row & 7) << 4);
    const u32 rb  = (u32)(row * 512);
    #pragma unroll
    for (int c = 0; c < 8; c++) {
        float4 q0 = qv[2 * c], q1 = qv[2 * c + 1];
        float4 p0 = pp[2 * c], p1 = pp[2 * c + 1];
        float v0 = fmaxf(p0.x + q0.x, 0.f), v1 = fmaxf(p0.y + q0.y, 0.f);
        float v2 = fmaxf(p0.z + q0.z, 0.f), v3 = fmaxf(p0.w + q0.w, 0.f);
        float v4 = fmaxf(p1.x + q1.x, 0.f), v5 = fmaxf(p1.y + q1.y, 0.f);
        float v6 = fmaxf(p1.z + q1.z, 0.f), v7 = fmaxf(p1.w + q1.w, 0.f);
        __half2 h01 = __floats2half2_rn(v0, v1);
        __half2 h23 = __floats2half2_rn(v2, v3);
        __half2 h45 = __floats2half2_rn(v4, v5);
        __half2 h67 = __floats2half2_rn(v6, v7);
        uint4 hi4;
        hi4.x = *(u32*)&h01; hi4.y = *(u32*)&h23;
        hi4.z = *(u32*)&h45; hi4.w = *(u32*)&h67;
        u32 off = (rb + (u32)(((ks >> 3) + c) * 16)) ^ swz;
        *(uint4*)(h1_p + off) = hi4;
    }
}

// ---------------------------------------------------------------------------
#define ROWS_PER_BLK 32
__global__ __launch_bounds__(256) void pq_kernel(
    const float* __restrict__ x, const float* __restrict__ W1,
    const float* __restrict__ b1)
{
    __shared__ float xs[ROWS_PER_BLK * D_DIM];
    const int t = threadIdx.x;
    const int row0 = blockIdx.x * ROWS_PER_BLK;

    const float4* xsrc = (const float4*)(x + (size_t)row0 * D_DIM);
    float4* xdst = (float4*)xs;
    #pragma unroll
    for (int i = 0; i < (ROWS_PER_BLK * D_DIM / 4) / 256; i++)
        xdst[t + i * 256] = xsrc[t + i * 256];
    __syncthreads();

    float accP[ROWS_PER_BLK], accQ[ROWS_PER_BLK];
    #pragma unroll
    for (int r = 0; r < ROWS_PER_BLK; r++) { accP[r] = 0.f; accQ[r] = 0.f; }

    #pragma unroll 2
    for (int d = 0; d < D_DIM; d++) {
        float wp = W1[d * H_DIM + t];
        float wq = W1[(D_DIM + d) * H_DIM + t];
        #pragma unroll
        for (int r = 0; r < ROWS_PER_BLK; r++) {
            float xv = xs[r * D_DIM + d];
            accP[r] = fmaf(xv, wp, accP[r]);
            accQ[r] = fmaf(xv, wq, accQ[r]);
        }
    }
    float bb = b1[t];
    #pragma unroll
    for (int r = 0; r < ROWS_PER_BLK; r++) {
        g_P[(size_t)(row0 + r) * H_DIM + t] = accP[r] + bb;
        g_Q[(size_t)(row0 + r) * H_DIM + t] = accQ[r];
    }
}

// ---------------------------------------------------------------------------
__global__ void w2prep_kernel(const float* __restrict__ W2) {
    const int k = blockIdx.x;      // 0..255
    const int n = threadIdx.x;     // 0..255
    float v = W2[k * H_DIM + n];
    __half h = __float2half(v);
    u32 off = (u32)(n * 512 + k * 2) ^ (u32)((n & 7) << 4);
    *(__half*)&g_W2h[off] = h;
}

// ---------------------------------------------------------------------------
// Persistent main kernel: one CTA per SM, 512 threads (16 warps), M=128.
// smem: W2 fp16 (128KB) + h1 (64KB, single buffer) + P stage (8KB).
// Warp tile 32x64: warp&3 -> 32-row quarter, warp>>2 -> 64-col quarter.
// Two barriers per group; epilogue warps 0-3 overlap next group's MMA.
// ---------------------------------------------------------------------------
#define SMEM_DYN (131072 + 65536 + 8192)

__global__ __launch_bounds__(THREADS, 1) void mlp_kernel(
    const int* __restrict__ nbrs,
    const float* __restrict__ t_arr, const float* __restrict__ e_hat,
    const float* __restrict__ b2, const float* __restrict__ W3,
    const float* __restrict__ b3, const float* __restrict__ b_scal,
    float* __restrict__ ypred, float* __restrict__ pairwise)
{
    extern __shared__ __align__(128) unsigned char dsm[];
    unsigned char* w2s_p = dsm;             // 128KB
    unsigned char* h1_p  = dsm + 131072;    // 64KB
    float*         P_s   = (float*)(dsm + 196608);  // 2 bufs x 1024 floats
    __shared__ int   cjs_all[MAXG * 128];
    __shared__ float red_s[2][4][128];
    __shared__ float b2s[H_DIM], w3s[H_DIM];

    const int tid  = threadIdx.x;
    const int lane = tid & 31;
    const int warp = tid >> 5;
    const int bid  = blockIdx.x;
    const int grid = gridDim.x;

    if (tid < H_DIM) { b2s[tid] = b2[tid]; w3s[tid] = W3[tid]; }

    const u32 w2sa = smem_u32(w2s_p);
    const u32 h1sa = smem_u32(h1_p);
    const u32 psb  = smem_u32(P_s);

    // load full W2 image once (128KB; 256B per thread)
    #pragma unroll
    for (int t = 0; t < 16; t++) {
        int idx = (t * THREADS + tid) * 16;
        cp_async16(w2sa + idx, g_W2h + idx);
    }
    cp_commit();

    // load all this CTA's neighbor indices once (MAXG*128 = 1792)
    #pragma unroll
    for (int i = 0; i < 4; i++) {
        int idx = i * THREADS + tid;
        if (idx < MAXG * 128) {
            int gp = bid + (idx >> 7) * grid;
            if (gp < NGROUPS) {
                int node = 4 * gp + ((idx >> 5) & 3);
                cjs_all[idx] = nbrs[node * (K_NB + 1) + 1 + (idx & 31)];
            }
        }
    }

    // stage P for group 0 into P_s buf 0 (4 nodes x 256 floats)
    if (tid < 256) {
        int nn = 4 * bid + (tid >> 6);
        *(float4*)(P_s + tid * 4) =
            *(const float4*)(g_P + (size_t)nn * H_DIM + (tid & 63) * 4);
    }
    __syncthreads();   // cjs_all, P_s[0], b2s/w3s ready

    const int row = tid >> 2, ks = (tid & 3) * 64;

    // build h1 for group 0
    build_slice(g_Q + (size_t)cjs_all[row] * H_DIM,
                P_s + (row >> 5) * 256, ks, row, h1_p);
    cp_wait0();
    __syncthreads();   // h1[0] + W2 visible

    // ---- MMA geometry: warp&3 -> 32-row quarter, warp>>2 -> 64-col quarter
    const int m_base = (warp & 3) * 32;
    const int n_base = (warp >> 2) * 64;
    const int kbA = (lane >> 4) * 8;
    const int nB7  = (lane & 7) + ((lane >> 4) & 1) * 8;
    const int kkB7 = ((lane >> 3) & 1) * 8;
    const int tig  = lane & 3;
    const int mA0 = m_base + ((lane >> 3) & 1) * 8 + (lane & 7);

    #pragma unroll 1
    for (int g = 0;; g++) {
        int gp = bid + g * grid;
        if (gp >= NGROUPS) break;
        int gpn = gp + grid;
        bool has_next = (gpn < NGROUPS);

        // ---- stage next group's P
        if (has_next && tid < 256) {
            int nn = 4 * gpn + (tid >> 6);
            cp_async16(psb + (u32)(((g + 1) & 1) * 4096 + tid * 16),
                       g_P + (size_t)nn * H_DIM + (tid & 63) * 4);
        }
        cp_commit();

        // ---- zero this group's pairwise rows (4 rows x 32KB)
        {
            float4 z = make_float4(0.f, 0.f, 0.f, 0.f);
            float4* b4 = (float4*)(pairwise + (size_t)gp * 4 * N_NODES);
            #pragma unroll
            for (int v = 0; v < 16; v++) b4[v * THREADS + tid] = z;
        }

        // ---- MMA mainloop on h1
        float cc[64];
        #pragma unroll
        for (int i = 0; i < 64; i++) cc[i] = 0.f;

        #pragma unroll 2
        for (int kt = 0; kt < 16; kt++) {
            u32 ah[2][4], bv[4][4];
            #pragma unroll
            for (int fm = 0; fm < 2; fm++) {
                int mA = mA0 + fm * 16;
                u32 offA = ((u32)(mA * 512 + (kt * 16 + kbA) * 2)) ^ (u32)((mA & 7) << 4);
                ldsm4(ah[fm], h1sa + offA);
            }
            #pragma unroll
            for (int fb = 0; fb < 4; fb++) {
                int nB = n_base + fb * 16 + nB7;
                u32 offB = ((u32)(nB * 512 + (kt * 16 + kkB7) * 2)) ^ (u32)((nB & 7) << 4);
                ldsm4(bv[fb], w2sa + offB);
            }
            #pragma unroll
            for (int fm = 0; fm < 2; fm++)
                #pragma unroll
                for (int fb = 0; fb < 4; fb++) {
                    mma_f16(cc + (fm * 8 + 2 * fb) * 4,     ah[fm], bv[fb]);
                    mma_f16(cc + (fm * 8 + 2 * fb + 1) * 4, ah[fm], bv[fb] + 2);
                }
        }

        // ---- fold relu(C + b2) . W3 per row into red_s[g&1]
        {
            float a0 = 0.f, a1 = 0.f, a2 = 0.f, a3 = 0.f;
            #pragma unroll
            for (int fm = 0; fm < 2; fm++) {
                #pragma unroll
                for (int fn = 0; fn < 8; fn++) {
                    int col = n_base + fn * 8 + 2 * tig;
                    float b0 = b2s[col], b1v = b2s[col + 1];
                    float w0 = w3s[col], w1v = w3s[col + 1];
                    const float* cf = cc + (fm * 8 + fn) * 4;
                    float s0 = fmaf(fmaxf(cf[0] + b0, 0.f), w0,
                                    fmaxf(cf[1] + b1v, 0.f) * w1v);
                    float s1 = fmaf(fmaxf(cf[2] + b0, 0.f), w0,
                                    fmaxf(cf[3] + b1v, 0.f) * w1v);
                    if (fm == 0) { a0 += s0; a1 += s1; }
                    else         { a2 += s0; a3 += s1; }
                }
            }
            a0 += __shfl_xor_sync(0xffffffffu, a0, 1);
            a0 += __shfl_xor_sync(0xffffffffu, a0, 2);
            a1 += __shfl_xor_sync(0xffffffffu, a1, 1);
            a1 += __shfl_xor_sync(0xffffffffu, a1, 2);
            a2 += __shfl_xor_sync(0xffffffffu, a2, 1);
            a2 += __shfl_xor_sync(0xffffffffu, a2, 2);
            a3 += __shfl_xor_sync(0xffffffffu, a3, 1);
            a3 += __shfl_xor_sync(0xffffffffu, a3, 2);
            if (tig == 0) {
                int rg = lane >> 2;
                float* rs = &red_s[g & 1][warp >> 2][0];
                rs[m_base + rg]      = a0;
                rs[m_base + 8 + rg]  = a1;
                rs[m_base + 16 + rg] = a2;
                rs[m_base + 24 + rg] = a3;
            }
        }

        __syncthreads();   // (A) all MMA reads of h1 done; red_s[g&1] visible

        // ---- build next group's h1 (single buffer, safe after barrier A)
        if (has_next) {
            cp_wait0();    // next P staged
            build_slice(g_Q + (size_t)cjs_all[(g + 1) * 128 + row] * H_DIM,
                        P_s + ((g + 1) & 1) * 1024 + (row >> 5) * 256, ks, row,
                        h1_p);
        }

        __syncthreads();   // (B) h1 next group ready; zero-STGs ordered

        // ---- epilogue: warps 0-3 handle node 4*gp+warp (overlaps next MMA)
        if (warp < 4) {
            const int j = lane;
            const int node = 4 * gp + warp;
            const int r0 = warp * 32 + j;
            const float* rs0 = &red_s[g & 1][0][0];
            float mlp = rs0[r0] + rs0[128 + r0] + rs0[256 + r0] + rs0[384 + r0]
                      + b3[0];
            int cj = cjs_all[g * 128 + r0];

            float a = b_scal[0] * fabsf(mlp);
            float amax = a;
            #pragma unroll
            for (int o = 16; o > 0; o >>= 1)
                amax = fmaxf(amax, __shfl_xor_sync(0xffffffffu, amax, o));
            float e = __expf(a - amax);
            float esum = e;
            #pragma unroll
            for (int o = 16; o > 0; o >>= 1)
                esum += __shfl_xor_sync(0xffffffffu, esum, o);
            float wgt = mlp * (e / esum);

            float prop = t_arr[cj] - e_hat[cj];
            float yp = prop * wgt;
            #pragma unroll
            for (int o = 16; o > 0; o >>= 1)
                yp += __shfl_xor_sync(0xffffffffu, yp, o);
            if (lane == 0) ypred[node] = yp;

            // parallel scatter: last-wins = highest lane of each match group
            float* prow = pairwise + (size_t)node * N_NODES;
            u32 mk = __match_any_sync(0xffffffffu, cj);
            int leader = 31 - __clz(mk);
            if (lane == leader && cj != node) prow[cj] = wgt;
            if (lane == 0) prow[node] = 0.f;
        }
    }
}

// ---------------------------------------------------------------------------
extern "C" void kernel_launch(void* const* d_in, const int* in_sizes, int n_in,
                              void* d_out, int out_size) {
    const float* x     = (const float*)d_in[0];
    const int*   nbrs  = (const int*)  d_in[1];
    const float* t_arr = (const float*)d_in[2];
    const float* e_hat = (const float*)d_in[3];
    const float* W1    = (const float*)d_in[4];
    const float* b1    = (const float*)d_in[5];
    const float* W2    = (const float*)d_in[6];
    const float* b2    = (const float*)d_in[7];
    const float* W3    = (const float*)d_in[8];
    const float* b3    = (const float*)d_in[9];
    const float* bsc   = (const float*)d_in[10];

    float* ypred    = (float*)d_out;
    float* pairwise = ypred + N_NODES;

    static int nsm = 0;
    if (!nsm) {
        cudaDeviceProp prop;
        cudaGetDeviceProperties(&prop, 0);
        nsm = prop.multiProcessorCount;
        if (nsm < 1) nsm = 148;
        cudaFuncSetAttribute(mlp_kernel,
                             cudaFuncAttributeMaxDynamicSharedMemorySize,
                             SMEM_DYN);
    }

    pq_kernel<<<N_NODES / ROWS_PER_BLK, 256>>>(x, W1, b1);
    w2prep_kernel<<<H_DIM, 256>>>(W2);
    mlp_kernel<<<nsm, THREADS, SMEM_DYN>>>(nbrs, t_arr, e_hat, b2, W3,
                                           b3, bsc, ypred, pairwise);
}

// round 17
// speedup vs baseline: 1.4381x; 1.4381x over previous
#include <cuda_runtime.h>
#include <cuda_fp16.h>
#include <cstdint>
#include <stdint.h>
#include <math.h>

#define N_NODES 8192
#define K_NB    32
#define D_DIM   128
#define H_DIM   256
#define NGROUPS 4096     // 2 nodes per group -> M = 64 rows
#define MAXG    28

typedef unsigned int       u32;
typedef unsigned long long u64;

__device__ __half g_Ph[N_NODES * H_DIM];   // fp16(x @ W1[:128] + b1)
__device__ __half g_Qh[N_NODES * H_DIM];   // fp16(x @ W1[128:])
// W2^T fp16 swizzled smem image: row n (512B = 256 k), 128KB
__device__ __align__(16) unsigned char g_W2h[131072];

// ---------------- helpers ----------------
__device__ __forceinline__ u32 smem_u32(const void* p) {
    return (u32)__cvta_generic_to_shared(p);
}
__device__ __forceinline__ void cp_async16(u32 saddr, const void* gaddr) {
    asm volatile("cp.async.cg.shared.global [%0], [%1], 16;" :: "r"(saddr), "l"(gaddr));
}
__device__ __forceinline__ void cp_commit() { asm volatile("cp.async.commit_group;"); }
__device__ __forceinline__ void cp_wait0() {
    asm volatile("cp.async.wait_group 0;" ::: "memory");
}
__device__ __forceinline__ void ldsm4(u32* r, u32 addr) {
    asm volatile("ldmatrix.sync.aligned.m8n8.x4.shared.b16 {%0,%1,%2,%3}, [%4];"
                 : "=r"(r[0]), "=r"(r[1]), "=r"(r[2]), "=r"(r[3]) : "r"(addr));
}
__device__ __forceinline__ void mma_f16(float* c, const u32* a, const u32* b) {
    asm volatile(
        "mma.sync.aligned.m16n8k16.row.col.f32.f16.f16.f32 "
        "{%0,%1,%2,%3}, {%4,%5,%6,%7}, {%8,%9}, {%0,%1,%2,%3};"
        : "+f"(c[0]), "+f"(c[1]), "+f"(c[2]), "+f"(c[3])
        : "r"(a[0]), "r"(a[1]), "r"(a[2]), "r"(a[3]), "r"(b[0]), "r"(b[1]));
}

// h1 slice (64 k-values) from preloaded fp16 P and Q register fragments
__device__ __forceinline__ void build_slice_h(
    const uint4* qv, const uint4* pv, int ks, int row,
    unsigned char* h1_p)
{
    const u32 swz = (u32)((row & 7) << 4);
    const u32 rb  = (u32)(row * 512);
    const __half2 z2 = __floats2half2_rn(0.f, 0.f);
    #pragma unroll
    for (int c = 0; c < 8; c++) {
        uint4 q4 = qv[c];
        uint4 p4 = pv[c];
        uint4 o4;
        __half2 a, b;
        a = *(__half2*)&q4.x; b = *(__half2*)&p4.x;
        a = __hmax2(__hadd2(a, b), z2); o4.x = *(u32*)&a;
        a = *(__half2*)&q4.y; b = *(__half2*)&p4.y;
        a = __hmax2(__hadd2(a, b), z2); o4.y = *(u32*)&a;
        a = *(__half2*)&q4.z; b = *(__half2*)&p4.z;
        a = __hmax2(__hadd2(a, b), z2); o4.z = *(u32*)&a;
        a = *(__half2*)&q4.w; b = *(__half2*)&p4.w;
        a = __hmax2(__hadd2(a, b), z2); o4.w = *(u32*)&a;
        u32 off = (rb + (u32)(((ks >> 3) + c) * 16)) ^ swz;
        *(uint4*)(h1_p + off) = o4;
    }
}

// ---------------------------------------------------------------------------
// PQ precompute -> fp16 outputs; float4 smem loads.
// ---------------------------------------------------------------------------
#define ROWS_PER_BLK 32
__global__ __launch_bounds__(256) void pq_kernel(
    const float* __restrict__ x, const float* __restrict__ W1,
    const float* __restrict__ b1)
{
    __shared__ float xs[ROWS_PER_BLK * D_DIM];
    const int t = threadIdx.x;
    const int row0 = blockIdx.x * ROWS_PER_BLK;

    const float4* xsrc = (const float4*)(x + (size_t)row0 * D_DIM);
    float4* xdst = (float4*)xs;
    #pragma unroll
    for (int i = 0; i < (ROWS_PER_BLK * D_DIM / 4) / 256; i++)
        xdst[t + i * 256] = xsrc[t + i * 256];
    __syncthreads();

    float accP[ROWS_PER_BLK], accQ[ROWS_PER_BLK];
    #pragma unroll
    for (int r = 0; r < ROWS_PER_BLK; r++) { accP[r] = 0.f; accQ[r] = 0.f; }

    const float4* xs4 = (const float4*)xs;
    #pragma unroll 2
    for (int d4 = 0; d4 < D_DIM / 4; d4++) {
        float wp0 = W1[(4 * d4 + 0) * H_DIM + t];
        float wp1 = W1[(4 * d4 + 1) * H_DIM + t];
        float wp2 = W1[(4 * d4 + 2) * H_DIM + t];
        float wp3 = W1[(4 * d4 + 3) * H_DIM + t];
        float wq0 = W1[(D_DIM + 4 * d4 + 0) * H_DIM + t];
        float wq1 = W1[(D_DIM + 4 * d4 + 1) * H_DIM + t];
        float wq2 = W1[(D_DIM + 4 * d4 + 2) * H_DIM + t];
        float wq3 = W1[(D_DIM + 4 * d4 + 3) * H_DIM + t];
        #pragma unroll
        for (int r = 0; r < ROWS_PER_BLK; r++) {
            float4 xv = xs4[r * (D_DIM / 4) + d4];
            accP[r] = fmaf(xv.x, wp0, fmaf(xv.y, wp1,
                      fmaf(xv.z, wp2, fmaf(xv.w, wp3, accP[r]))));
            accQ[r] = fmaf(xv.x, wq0, fmaf(xv.y, wq1,
                      fmaf(xv.z, wq2, fmaf(xv.w, wq3, accQ[r]))));
        }
    }
    float bb = b1[t];
    #pragma unroll
    for (int r = 0; r < ROWS_PER_BLK; r++) {
        g_Ph[(size_t)(row0 + r) * H_DIM + t] = __float2half(accP[r] + bb);
        g_Qh[(size_t)(row0 + r) * H_DIM + t] = __float2half(accQ[r]);
    }
}

// ---------------------------------------------------------------------------
__global__ void w2prep_kernel(const float* __restrict__ W2) {
    const int k = blockIdx.x;      // 0..255
    const int n = threadIdx.x;     // 0..255
    float v = W2[k * H_DIM + n];
    __half h = __float2half(v);
    u32 off = (u32)(n * 512 + k * 2) ^ (u32)((n & 7) << 4);
    *(__half*)&g_W2h[off] = h;
}

// ---------------------------------------------------------------------------
// Persistent main kernel: one CTA per SM, 256 threads (8 warps), M=64.
// smem: W2 fp16 (128KB) + h1 double buffer (2x32KB) = 192KB.
// P AND Q for the next group preloaded into REGISTERS at loop top (no smem
// staging, no cp.async in loop -> no producer/consumer race). One
// __syncthreads per group; epilogue warps 0/1 overlap next group's MMA.
// ---------------------------------------------------------------------------
#define SMEM_DYN (131072 + 65536)

__global__ __launch_bounds__(256, 1) void mlp_kernel(
    const int* __restrict__ nbrs,
    const float* __restrict__ t_arr, const float* __restrict__ e_hat,
    const float* __restrict__ b2, const float* __restrict__ W3,
    const float* __restrict__ b3, const float* __restrict__ b_scal,
    float* __restrict__ ypred, float* __restrict__ pairwise)
{
    extern __shared__ __align__(128) unsigned char dsm[];
    unsigned char* w2s_p = dsm;             // 128KB
    unsigned char* h1b_p = dsm + 131072;    // 2 x 32KB
    __shared__ int   cjs_all[MAXG * 64];
    __shared__ float red_s[2][4][64];
    __shared__ float b2s[H_DIM], w3s[H_DIM];

    const int tid  = threadIdx.x;
    const int lane = tid & 31;
    const int warp = tid >> 5;
    const int bid  = blockIdx.x;
    const int grid = gridDim.x;

    b2s[tid] = b2[tid];
    w3s[tid] = W3[tid];

    const u32 w2sa  = smem_u32(w2s_p);
    const u32 h1sa0 = smem_u32(h1b_p);

    // load full W2 image once (128KB; 512B per thread)
    #pragma unroll
    for (int t = 0; t < 32; t++) {
        int idx = (t * 256 + tid) * 16;
        cp_async16(w2sa + idx, g_W2h + idx);
    }
    cp_commit();

    // load all this CTA's neighbor indices once
    #pragma unroll
    for (int i = 0; i < 7; i++) {
        int idx = i * 256 + tid;
        int g8 = idx >> 6;
        int gp = bid + g8 * grid;
        if (idx < MAXG * 64 && gp < NGROUPS)
            cjs_all[idx] = nbrs[(2 * gp + ((idx >> 5) & 1)) * (K_NB + 1) + 1 + (idx & 31)];
    }
    __syncthreads();   // cjs_all, b2s/w3s ready

    const int row = tid >> 2, ks = (tid & 3) * 64;
    const int nodeslot = row >> 5;   // 0/1 within group

    // build h1 for group 0 into buffer 0 (P and Q via registers)
    {
        uint4 qv0[8], pv0[8];
        const uint4* Qp = (const uint4*)(g_Qh + (size_t)cjs_all[row] * H_DIM + ks);
        const uint4* Pp = (const uint4*)(g_Ph + (size_t)(2 * bid + nodeslot) * H_DIM + ks);
        #pragma unroll
        for (int i = 0; i < 8; i++) { qv0[i] = Qp[i]; pv0[i] = Pp[i]; }
        build_slice_h(qv0, pv0, ks, row, (unsigned char*)h1b_p);
    }
    cp_wait0();
    __syncthreads();   // h1[0] + W2 visible

    // ---- MMA geometry: warp&1 -> 32-row half, warp>>1 -> 64-col quarter
    const int m_base = (warp & 1) * 32;
    const int n_base = (warp >> 1) * 64;
    const int kbA = (lane >> 4) * 8;
    const int nB7  = (lane & 7) + ((lane >> 4) & 1) * 8;
    const int kkB7 = ((lane >> 3) & 1) * 8;
    const int tig  = lane & 3;
    const int mA0 = m_base + ((lane >> 3) & 1) * 8 + (lane & 7);

    #pragma unroll 1
    for (int g = 0;; g++) {
        int gp = bid + g * grid;
        if (gp >= NGROUPS) break;
        int gpn = gp + grid;
        bool has_next = (gpn < NGROUPS);

        // ---- loop top: preload next group's P and Q into registers
        uint4 qv[8], pv[8];
        if (has_next) {
            const uint4* Qp = (const uint4*)
                (g_Qh + (size_t)cjs_all[(g + 1) * 64 + row] * H_DIM + ks);
            const uint4* Pp = (const uint4*)
                (g_Ph + (size_t)(2 * gpn + nodeslot) * H_DIM + ks);
            #pragma unroll
            for (int i = 0; i < 8; i++) { qv[i] = Qp[i]; pv[i] = Pp[i]; }
        }

        // ---- zero this group's pairwise rows (2 rows x 32KB)
        {
            float4 z = make_float4(0.f, 0.f, 0.f, 0.f);
            float4* b4 = (float4*)(pairwise + (size_t)gp * 2 * N_NODES);
            #pragma unroll
            for (int v = 0; v < 16; v++) b4[v * 256 + tid] = z;
        }

        // ---- MMA mainloop on h1[g&1]
        const u32 h1sa = h1sa0 + (u32)((g & 1) * 32768);
        float cc[64];
        #pragma unroll
        for (int i = 0; i < 64; i++) cc[i] = 0.f;

        #pragma unroll 2
        for (int kt = 0; kt < 16; kt++) {
            u32 ah[2][4], bv[4][4];
            #pragma unroll
            for (int fm = 0; fm < 2; fm++) {
                int mA = mA0 + fm * 16;
                u32 offA = ((u32)(mA * 512 + (kt * 16 + kbA) * 2)) ^ (u32)((mA & 7) << 4);
                ldsm4(ah[fm], h1sa + offA);
            }
            #pragma unroll
            for (int fb = 0; fb < 4; fb++) {
                int nB = n_base + fb * 16 + nB7;
                u32 offB = ((u32)(nB * 512 + (kt * 16 + kkB7) * 2)) ^ (u32)((nB & 7) << 4);
                ldsm4(bv[fb], w2sa + offB);
            }
            #pragma unroll
            for (int fm = 0; fm < 2; fm++)
                #pragma unroll
                for (int fb = 0; fb < 4; fb++) {
                    mma_f16(cc + (fm * 8 + 2 * fb) * 4,     ah[fm], bv[fb]);
                    mma_f16(cc + (fm * 8 + 2 * fb + 1) * 4, ah[fm], bv[fb] + 2);
                }
        }

        // ---- fold relu(C + b2) . W3 per row into red_s[g&1]
        {
            float a0 = 0.f, a1 = 0.f, a2 = 0.f, a3 = 0.f;
            #pragma unroll
            for (int fm = 0; fm < 2; fm++) {
                #pragma unroll
                for (int fn = 0; fn < 8; fn++) {
                    int col = n_base + fn * 8 + 2 * tig;
                    float b0 = b2s[col], b1v = b2s[col + 1];
                    float w0 = w3s[col], w1v = w3s[col + 1];
                    const float* cf = cc + (fm * 8 + fn) * 4;
                    float s0 = fmaf(fmaxf(cf[0] + b0, 0.f), w0,
                                    fmaxf(cf[1] + b1v, 0.f) * w1v);
                    float s1 = fmaf(fmaxf(cf[2] + b0, 0.f), w0,
                                    fmaxf(cf[3] + b1v, 0.f) * w1v);
                    if (fm == 0) { a0 += s0; a1 += s1; }
                    else         { a2 += s0; a3 += s1; }
                }
            }
            a0 += __shfl_xor_sync(0xffffffffu, a0, 1);
            a0 += __shfl_xor_sync(0xffffffffu, a0, 2);
            a1 += __shfl_xor_sync(0xffffffffu, a1, 1);
            a1 += __shfl_xor_sync(0xffffffffu, a1, 2);
            a2 += __shfl_xor_sync(0xffffffffu, a2, 1);
            a2 += __shfl_xor_sync(0xffffffffu, a2, 2);
            a3 += __shfl_xor_sync(0xffffffffu, a3, 1);
            a3 += __shfl_xor_sync(0xffffffffu, a3, 2);
            if (tig == 0) {
                int rg = lane >> 2;
                float* rs = &red_s[g & 1][warp >> 1][0];
                rs[m_base + rg]      = a0;
                rs[m_base + 8 + rg]  = a1;
                rs[m_base + 16 + rg] = a2;
                rs[m_base + 24 + rg] = a3;
            }
        }

        // ---- build next group's h1 into buffer (g+1)&1 (P/Q in registers)
        if (has_next)
            build_slice_h(qv, pv, ks, row, h1b_p + ((g + 1) & 1) * 32768);

        __syncthreads();   // h1[(g+1)&1], red_s[g&1], zero-STGs all ordered

        // ---- epilogue: warps 0/1 handle node 2*gp+warp (overlaps next MMA)
        if (warp < 2) {
            const int j = lane;
            const int node = 2 * gp + warp;
            const float* rs0 = &red_s[g & 1][0][0];
            float mlp = rs0[warp * 32 + j] + rs0[64 + warp * 32 + j]
                      + rs0[128 + warp * 32 + j] + rs0[192 + warp * 32 + j] + b3[0];
            int cj = cjs_all[g * 64 + warp * 32 + j];

            float a = b_scal[0] * fabsf(mlp);
            float amax = a;
            #pragma unroll
            for (int o = 16; o > 0; o >>= 1)
                amax = fmaxf(amax, __shfl_xor_sync(0xffffffffu, amax, o));
            float e = __expf(a - amax);
            float esum = e;
            #pragma unroll
            for (int o = 16; o > 0; o >>= 1)
                esum += __shfl_xor_sync(0xffffffffu, esum, o);
            float wgt = mlp * (e / esum);

            float prop = t_arr[cj] - e_hat[cj];
            float yp = prop * wgt;
            #pragma unroll
            for (int o = 16; o > 0; o >>= 1)
                yp += __shfl_xor_sync(0xffffffffu, yp, o);
            if (lane == 0) ypred[node] = yp;

            // parallel scatter: last-wins = highest lane of each match group
            float* prow = pairwise + (size_t)node * N_NODES;
            u32 mk = __match_any_sync(0xffffffffu, cj);
            int leader = 31 - __clz(mk);
            if (lane == leader && cj != node) prow[cj] = wgt;
            if (lane == 0) prow[node] = 0.f;
        }
    }
}

// ---------------------------------------------------------------------------
extern "C" void kernel_launch(void* const* d_in, const int* in_sizes, int n_in,
                              void* d_out, int out_size) {
    const float* x     = (const float*)d_in[0];
    const int*   nbrs  = (const int*)  d_in[1];
    const float* t_arr = (const float*)d_in[2];
    const float* e_hat = (const float*)d_in[3];
    const float* W1    = (const float*)d_in[4];
    const float* b1    = (const float*)d_in[5];
    const float* W2    = (const float*)d_in[6];
    const float* b2    = (const float*)d_in[7];
    const float* W3    = (const float*)d_in[8];
    const float* b3    = (const float*)d_in[9];
    const float* bsc   = (const float*)d_in[10];

    float* ypred    = (float*)d_out;
    float* pairwise = ypred + N_NODES;

    static int nsm = 0;
    if (!nsm) {
        cudaDeviceProp prop;
        cudaGetDeviceProperties(&prop, 0);
        nsm = prop.multiProcessorCount;
        if (nsm < 1) nsm = 148;
        cudaFuncSetAttribute(mlp_kernel,
                             cudaFuncAttributeMaxDynamicSharedMemorySize,
                             SMEM_DYN);
    }

    pq_kernel<<<N_NODES / ROWS_PER_BLK, 256>>>(x, W1, b1);
    w2prep_kernel<<<H_DIM, 256>>>(W2);
    mlp_kernel<<<nsm, 256, SMEM_DYN>>>(nbrs, t_arr, e_hat, b2, W3,
                                       b3, bsc, ypred, pairwise);
}